// round 5
// baseline (speedup 1.0000x reference)
#include <cuda_runtime.h>

#define NUM_LEVELS 256

__device__ __forceinline__ float quantize_one(float v) {
    // Nearest center of linspace(-1, 1, 256): i = round((v+1)*127.5), clamped.
    float t = fmaf(v, 127.5f, 127.5f);
    float fi = rintf(t);
    fi = fmaxf(0.0f, fminf(255.0f, fi));
    // Reconstruct center: -1 + i * (2/255)
    return fmaf(fi, 2.0f / 255.0f, -1.0f);
}

__device__ __forceinline__ float4 quantize_vec(float4 v) {
    float4 o;
    o.x = quantize_one(v.x);
    o.y = quantize_one(v.y);
    o.z = quantize_one(v.z);
    o.w = quantize_one(v.w);
    return o;
}

#define UNROLL 2

__global__ void __launch_bounds__(256) nq_kernel(
    const float4* __restrict__ x4,
    float4* __restrict__ out4,
    int n4)
{
    int base = blockIdx.x * (blockDim.x * UNROLL) + threadIdx.x;
    const int s = blockDim.x;

    if (base + (UNROLL - 1) * s < n4) {
        // Two independent streaming loads issued back-to-back.
        float4 v0 = __ldcs(&x4[base + 0 * s]);
        float4 v1 = __ldcs(&x4[base + 1 * s]);
        __stcs(&out4[base + 0 * s], quantize_vec(v0));
        __stcs(&out4[base + 1 * s], quantize_vec(v1));
    } else {
        #pragma unroll
        for (int u = 0; u < UNROLL; u++) {
            int idx = base + u * s;
            if (idx < n4) {
                float4 v = __ldcs(&x4[idx]);
                __stcs(&out4[idx], quantize_vec(v));
            }
        }
    }
}

__global__ void __launch_bounds__(256) nq_tail_kernel(
    const float* __restrict__ x,
    float* __restrict__ out,
    int start, int n)
{
    int i = start + blockIdx.x * blockDim.x + threadIdx.x;
    if (i < n) out[i] = quantize_one(x[i]);
}

extern "C" void kernel_launch(void* const* d_in, const int* in_sizes, int n_in,
                              void* d_out, int out_size) {
    const float* x = (const float*)d_in[0];
    float* out = (float*)d_out;
    int n = in_sizes[0];

    int n4 = n / 4;
    if (n4 > 0) {
        const int threads = 256;
        int per_block = threads * UNROLL;
        int blocks = (n4 + per_block - 1) / per_block;
        nq_kernel<<<blocks, threads>>>((const float4*)x, (float4*)out, n4);
    }
    int tail_start = n4 * 4;
    int tail = n - tail_start;
    if (tail > 0) {
        nq_tail_kernel<<<1, 256>>>(x, out, tail_start, n);
    }
}